// round 16
// baseline (speedup 1.0000x reference)
#include <cuda_runtime.h>
#include <cuda_bf16.h>

#define NN 16384
#define CC 1000
#define AA 768
#define AA2 (AA / 2)          // u32 (bf16x2) words per row
#define BINW 96

// ---------------- scratch (no allocs allowed; zero-initialized at load) ----------------
__device__ int g_cnt[CC];
__device__ int g_bin[CC * BINW];
__device__ float g_T3[CC];
__device__ __align__(16) unsigned g_Acov[CC * AA2];  // bf16x2(new_cov)
__device__ __align__(16) unsigned g_AP[CC * AA2];    // bf16x2(W * new_cov)
__device__ __align__(16) unsigned g_Bsq[CC * AA2];   // bf16x2(W^2)
__device__ __align__(16) unsigned g_Bm2[CC * AA2];   // bf16x2(-2W)
__device__ __align__(16) float g_S1[CC * CC];        // hr*(sum cov*W^2 + T3)
__device__ __align__(16) float g_S2[CC * CC];        // hr*(-2 sum P*W)

__device__ __forceinline__ int clamp_class(int c) {
    return (c < 0) ? 0 : ((c >= CC) ? CC - 1 : c);
}

__device__ __forceinline__ unsigned packbf2(float lo, float hi) {
    __nv_bfloat162 v = __floats2bfloat162_rn(lo, hi);
    return *(unsigned*)&v;
}

__device__ __forceinline__ void cpa16(unsigned dst, const void* src) {
    asm volatile("cp.async.cg.shared.global [%0], [%1], 16;" ::
                 "r"(dst), "l"(src));
}

__device__ __forceinline__ void ldsm4(unsigned& r0, unsigned& r1,
                                      unsigned& r2, unsigned& r3,
                                      unsigned addr) {
    asm volatile("ldmatrix.sync.aligned.m8n8.x4.shared.b16 {%0,%1,%2,%3}, [%4];"
                 : "=r"(r0), "=r"(r1), "=r"(r2), "=r"(r3) : "r"(addr));
}

// ---------------- direct binning scatter (g_cnt zeroed by k_out each run) ----------------
__global__ void k_scatter(const int* __restrict__ labels) {
    int n = blockIdx.x * 256 + threadIdx.x;   // 64*256 = NN
    int c = clamp_class(labels[n]);
    int p = atomicAdd(&g_cnt[c], 1);
    if (p < BINW) g_bin[c * BINW + p] = n;
}

// ---------------- per-class stats -> bf16x2 GEMM operands + T3 ----------------
__global__ void k_stats(const float* __restrict__ feats,
                        const float* __restrict__ W,
                        const float* __restrict__ count_in,
                        const float* __restrict__ mean_in,
                        const float* __restrict__ cov_in) {
    int c = blockIdx.x;
    int t = threadIdx.x;   // 0..191
    int mraw = g_cnt[c];   // NOT reset here; k_out resets after its use
    float cnt = (float)mraw;
    int m = (mraw < BINW) ? mraw : BINW;
    const int* bin = g_bin + c * BINW;

    float4 s = make_float4(0.f, 0.f, 0.f, 0.f);
    float4 q = make_float4(0.f, 0.f, 0.f, 0.f);

    int i = 0;
    for (; i + 4 <= m; i += 4) {
        int n0 = bin[i], n1 = bin[i + 1], n2 = bin[i + 2], n3 = bin[i + 3];
        float4 v0 = ((const float4*)(feats + (long)n0 * AA))[t];
        float4 v1 = ((const float4*)(feats + (long)n1 * AA))[t];
        float4 v2 = ((const float4*)(feats + (long)n2 * AA))[t];
        float4 v3 = ((const float4*)(feats + (long)n3 * AA))[t];
        s.x += v0.x + v1.x + v2.x + v3.x;
        s.y += v0.y + v1.y + v2.y + v3.y;
        s.z += v0.z + v1.z + v2.z + v3.z;
        s.w += v0.w + v1.w + v2.w + v3.w;
        q.x += v0.x * v0.x + v1.x * v1.x + v2.x * v2.x + v3.x * v3.x;
        q.y += v0.y * v0.y + v1.y * v1.y + v2.y * v2.y + v3.y * v3.y;
        q.z += v0.z * v0.z + v1.z * v1.z + v2.z * v2.z + v3.z * v3.z;
        q.w += v0.w * v0.w + v1.w * v1.w + v2.w * v2.w + v3.w * v3.w;
    }
    for (; i < m; i++) {
        float4 v = ((const float4*)(feats + (long)bin[i] * AA))[t];
        s.x += v.x; s.y += v.y; s.z += v.z; s.w += v.w;
        q.x += v.x * v.x; q.y += v.y * v.y;
        q.z += v.z * v.z; q.w += v.w * v.w;
    }

    float amount = fmaxf(cnt, 1.0f);
    float denom = cnt + count_in[c];
    float w = (denom > 0.0f) ? (cnt / fmaxf(denom, 1.0f)) : 0.0f;
    float omw = 1.0f - w;

    float sums[4] = {s.x, s.y, s.z, s.w};
    float sqs[4]  = {q.x, q.y, q.z, q.w};
    float nc[4], pv[4], wsq[4], wm2[4];
    float t3 = 0.0f;
#pragma unroll
    for (int j = 0; j < 4; j++) {
        int a = 4 * t + j;
        long idx = (long)c * AA + a;
        float ave = sums[j] / amount;
        float var = (sqs[j] - 2.0f * ave * sums[j] + cnt * ave * ave) / amount;
        float d = mean_in[idx] - ave;
        float v = cov_in[idx] * omw + var * w + w * omw * d * d;
        float wv = W[idx];
        nc[j] = v;
        pv[j] = wv * v;
        wsq[j] = wv * wv;
        wm2[j] = -2.0f * wv;
        t3 += wv * wv * v;
    }
    long o2 = (long)c * AA2 + 2 * t;
    g_Acov[o2]     = packbf2(nc[0], nc[1]);
    g_Acov[o2 + 1] = packbf2(nc[2], nc[3]);
    g_AP[o2]       = packbf2(pv[0], pv[1]);
    g_AP[o2 + 1]   = packbf2(pv[2], pv[3]);
    g_Bsq[o2]      = packbf2(wsq[0], wsq[1]);
    g_Bsq[o2 + 1]  = packbf2(wsq[2], wsq[3]);
    g_Bm2[o2]      = packbf2(wm2[0], wm2[1]);
    g_Bm2[o2 + 1]  = packbf2(wm2[2], wm2[3]);

    __shared__ float stot;
    if (t == 0) stot = 0.f;
    __syncthreads();
#pragma unroll
    for (int d2 = 16; d2 > 0; d2 >>= 1)
        t3 += __shfl_down_sync(0xffffffffu, t3, d2);
    if ((t & 31) == 0) atomicAdd(&stot, t3);
    __syncthreads();
    if (t == 0) g_T3[c] = stot;
}

// ---------------- tensor-core GEMM (bf16 m16n8k16, ldmatrix, phase-split-K) ----------------
// z=0: S1 = hr*(cov @ (W^2)^T + T3)   z=1: S2 = hr*(P @ (-2W)^T)
// Block 128(m) x 64(n), 256 threads = 8 warps (4m x 2n), warp tile 32x32.
// 3-buffer cp.async ring, ONE __syncthreads per stage, wait_group 1.
#define BM 128
#define BN 64
#define BKU 16   // u32 words per row per stage (= 32 bf16)
#define LDK 20   // padded u32 stride; ldmatrix-conflict-free
#define NSTG 3
#define STAGES (AA2 / BKU)   // 24
__global__ void __launch_bounds__(256, 2)
k_gemm_t(const float* __restrict__ ratio) {
    __shared__ unsigned sA[NSTG][BM * LDK];
    __shared__ unsigned sB[NSTG][BN * LDK];

    int tid = threadIdx.x;
    int bm = blockIdx.y * BM;
    int bn = blockIdx.x * BN;
    int z  = blockIdx.z;
    int lane = tid & 31;
    int warp = tid >> 5;
    int wm = (warp >> 1) * 32;
    int wn = (warp & 1) * 32;
    int grp = lane >> 2;
    int tig = lane & 3;

    const unsigned* Asrc = z ? g_AP : g_Acov;
    const unsigned* Bsrc = z ? g_Bm2 : g_Bsq;
    float* Sdst = z ? g_S2 : g_S1;

    int ar = tid >> 1;
    int ak = (tid & 1) * 8;
    int agm = bm + ar; if (agm >= CC) agm = CC - 1;
    int br = tid >> 2;
    int bk = (tid & 3) * 4;
    int bgn = bn + br; if (bgn >= CC) bgn = CC - 1;

    unsigned sa_dst[NSTG], sb_dst[NSTG];
#pragma unroll
    for (int b = 0; b < NSTG; b++) {
        sa_dst[b] = (unsigned)__cvta_generic_to_shared(&sA[b][ar * LDK + ak]);
        sb_dst[b] = (unsigned)__cvta_generic_to_shared(&sB[b][br * LDK + bk]);
    }

    int a_row_off = (lane & 7) + ((lane >> 3 & 1) << 3);
    int a_word    = (lane >> 4) << 2;
    int b_row_off = ((lane >> 4) << 3) + (lane & 7);
    int b_word    = ((lane >> 3) & 1) << 2;

    unsigned sA_base = (unsigned)__cvta_generic_to_shared(&sA[0][0]);
    unsigned sB_base = (unsigned)__cvta_generic_to_shared(&sB[0][0]);

    float acc[2][4][4];
#pragma unroll
    for (int mi = 0; mi < 2; mi++)
#pragma unroll
        for (int ni = 0; ni < 4; ni++)
#pragma unroll
            for (int q = 0; q < 4; q++) acc[mi][ni][q] = 0.f;

    auto issue = [&](int s, int buf) {
        int k0 = s * BKU;
        const unsigned* ap = Asrc + (long)agm * AA2 + k0 + ak;
        cpa16(sa_dst[buf], ap);
        cpa16(sa_dst[buf] + 16, ap + 4);
        cpa16(sb_dst[buf], Bsrc + (long)bgn * AA2 + k0 + bk);
        asm volatile("cp.async.commit_group;");
    };

    issue(0, 0);
    issue(1, 1);

    int buf = 0;
    int nbuf = 2;
    for (int s = 0; s < STAGES; s++) {
        if (s + 1 < STAGES) {
            asm volatile("cp.async.wait_group 1;");
        } else {
            asm volatile("cp.async.wait_group 0;");
        }
        __syncthreads();
        if (s + 2 < STAGES) issue(s + 2, nbuf);

        unsigned abase = sA_base + (buf * BM * LDK) * 4u;
        unsigned bbase = sB_base + (buf * BN * LDK) * 4u;
#pragma unroll
        for (int kk = 0; kk < 2; kk++) {
            int k8 = kk * 8;
            unsigned af[2][4];
#pragma unroll
            for (int mi = 0; mi < 2; mi++) {
                int rb = wm + mi * 16;
                unsigned addr = abase +
                    ((rb + a_row_off) * LDK + k8 + a_word) * 4u;
                ldsm4(af[mi][0], af[mi][1], af[mi][2], af[mi][3], addr);
            }
            unsigned bf[4][2];
#pragma unroll
            for (int np = 0; np < 2; np++) {
                int nb = wn + np * 16;
                unsigned addr = bbase +
                    ((nb + b_row_off) * LDK + k8 + b_word) * 4u;
                ldsm4(bf[np * 2][0], bf[np * 2][1],
                      bf[np * 2 + 1][0], bf[np * 2 + 1][1], addr);
            }
#pragma unroll
            for (int mi = 0; mi < 2; mi++)
#pragma unroll
                for (int ni = 0; ni < 4; ni++) {
                    float* c = acc[mi][ni];
                    asm volatile(
                        "mma.sync.aligned.m16n8k16.row.col.f32.bf16.bf16.f32 "
                        "{%0,%1,%2,%3}, {%4,%5,%6,%7}, {%8,%9}, {%0,%1,%2,%3};"
                        : "+f"(c[0]), "+f"(c[1]), "+f"(c[2]), "+f"(c[3])
                        : "r"(af[mi][0]), "r"(af[mi][1]),
                          "r"(af[mi][2]), "r"(af[mi][3]),
                          "r"(bf[ni][0]), "r"(bf[ni][1]));
                }
        }
        buf = (buf == NSTG - 1) ? 0 : buf + 1;
        nbuf = (nbuf == NSTG - 1) ? 0 : nbuf + 1;
    }

    float hr = 0.5f * ratio[0];
#pragma unroll
    for (int mi = 0; mi < 2; mi++) {
        int gm0 = bm + wm + mi * 16 + grp;
        int gm1 = gm0 + 8;
        float t30 = 0.f, t31 = 0.f;
        if (z == 0) {                  // fold T3 into S1
            t30 = (gm0 < CC) ? g_T3[gm0] : 0.f;
            t31 = (gm1 < CC) ? g_T3[gm1] : 0.f;
        }
#pragma unroll
        for (int ni = 0; ni < 4; ni++) {
            int gn = bn + wn + ni * 8 + tig * 2;
            if (gn < CC) {
                if (gm0 < CC)
                    *(float2*)&Sdst[(long)gm0 * CC + gn] =
                        make_float2(hr * (acc[mi][ni][0] + t30),
                                    hr * (acc[mi][ni][1] + t30));
                if (gm1 < CC)
                    *(float2*)&Sdst[(long)gm1 * CC + gn] =
                        make_float2(hr * (acc[mi][ni][2] + t31),
                                    hr * (acc[mi][ni][3] + t31));
            }
        }
    }
}

// ---------------- epilogue (class-major): one block per class ----------------
// out[n,:] = y[n,:] + (S1[c,:]+S2[c,:]) for every n in class c's bin.
// No per-element label loads, no dependent S gather; S row lives in SMEM.
#define C4 (CC / 4)            // 250 float4 per row
__global__ void __launch_bounds__(256)
k_out(const float* __restrict__ y, float* __restrict__ out) {
    int c = blockIdx.x;
    int t = threadIdx.x;   // 0..255

    __shared__ __align__(16) float4 sS[C4];
    int m = g_cnt[c];
    if (m > BINW) m = BINW;
    __shared__ int sbin[BINW];

    if (t < C4) {
        float4 a = ((const float4*)(g_S1 + (long)c * CC))[t];
        float4 b = ((const float4*)(g_S2 + (long)c * CC))[t];
        a.x += b.x; a.y += b.y; a.z += b.z; a.w += b.w;
        sS[t] = a;
    }
    if (t < BINW && t < m) sbin[t] = g_bin[c * BINW + t];
    __syncthreads();
    if (t == 0) g_cnt[c] = 0;   // reset for next launch (after all reads)

    if (t >= C4) return;
    float4 sv = sS[t];

    int r = 0;
    for (; r + 2 <= m; r += 2) {
        long n0 = sbin[r], n1 = sbin[r + 1];
        float4 a0 = ((const float4*)y)[n0 * C4 + t];
        float4 a1 = ((const float4*)y)[n1 * C4 + t];
        a0.x += sv.x; a0.y += sv.y; a0.z += sv.z; a0.w += sv.w;
        a1.x += sv.x; a1.y += sv.y; a1.z += sv.z; a1.w += sv.w;
        ((float4*)out)[n0 * C4 + t] = a0;
        ((float4*)out)[n1 * C4 + t] = a1;
    }
    if (r < m) {
        long n0 = sbin[r];
        float4 a0 = ((const float4*)y)[n0 * C4 + t];
        a0.x += sv.x; a0.y += sv.y; a0.z += sv.z; a0.w += sv.w;
        ((float4*)out)[n0 * C4 + t] = a0;
    }
}

// ---------------- launch ----------------
extern "C" void kernel_launch(void* const* d_in, const int* in_sizes, int n_in,
                              void* d_out, int out_size) {
    const float* y      = (const float*)d_in[0];
    const float* feats  = (const float*)d_in[1];
    const float* W      = (const float*)d_in[2];
    const int*   labels = (const int*)d_in[3];   // JAX x64 disabled -> int32
    const float* count  = (const float*)d_in[4];
    const float* mean   = (const float*)d_in[5];
    const float* cov    = (const float*)d_in[6];
    const float* ratio  = (const float*)d_in[7];
    float* out = (float*)d_out;

    k_scatter<<<NN / 256, 256>>>(labels);
    k_stats<<<CC, 192>>>(feats, W, count, mean, cov);
    k_gemm_t<<<dim3((CC + BN - 1) / BN, (CC + BM - 1) / BM, 2), 256>>>(ratio);
    k_out<<<CC, 256>>>(y, out);
}

// round 17
// speedup vs baseline: 1.0364x; 1.0364x over previous
#include <cuda_runtime.h>
#include <cuda_bf16.h>

#define NN 16384
#define CC 1000
#define AA 768
#define AA2 (AA / 2)          // u32 (bf16x2) words per row
#define BINW 96

// ---------------- scratch (no allocs allowed; zero-initialized at load) ----------------
__device__ int g_cnt[CC];
__device__ int g_bin[CC * BINW];
__device__ float g_T3[CC];
__device__ __align__(16) unsigned g_Acov[CC * AA2];  // bf16x2(new_cov)
__device__ __align__(16) unsigned g_AP[CC * AA2];    // bf16x2(W * new_cov)
__device__ __align__(16) unsigned g_Bsq[CC * AA2];   // bf16x2(W^2)
__device__ __align__(16) unsigned g_Bm2[CC * AA2];   // bf16x2(-2W)
__device__ __align__(16) float g_S1[CC * CC];        // hr*(sum cov*W^2 + T3)
__device__ __align__(16) float g_S2[CC * CC];        // hr*(-2 sum P*W)

__device__ __forceinline__ int clamp_class(int c) {
    return (c < 0) ? 0 : ((c >= CC) ? CC - 1 : c);
}

__device__ __forceinline__ unsigned packbf2(float lo, float hi) {
    __nv_bfloat162 v = __floats2bfloat162_rn(lo, hi);
    return *(unsigned*)&v;
}

__device__ __forceinline__ void cpa16(unsigned dst, const void* src) {
    asm volatile("cp.async.cg.shared.global [%0], [%1], 16;" ::
                 "r"(dst), "l"(src));
}

__device__ __forceinline__ void ldsm4(unsigned& r0, unsigned& r1,
                                      unsigned& r2, unsigned& r3,
                                      unsigned addr) {
    asm volatile("ldmatrix.sync.aligned.m8n8.x4.shared.b16 {%0,%1,%2,%3}, [%4];"
                 : "=r"(r0), "=r"(r1), "=r"(r2), "=r"(r3) : "r"(addr));
}

// ---------------- direct binning scatter (g_cnt zeroed by k_stats each run) ----------------
__global__ void k_scatter(const int* __restrict__ labels) {
    int n = blockIdx.x * 256 + threadIdx.x;   // 64*256 = NN
    int c = clamp_class(labels[n]);
    int p = atomicAdd(&g_cnt[c], 1);
    if (p < BINW) g_bin[c * BINW + p] = n;
}

// ---------------- per-class stats -> bf16x2 GEMM operands + T3 ----------------
__global__ void k_stats(const float* __restrict__ feats,
                        const float* __restrict__ W,
                        const float* __restrict__ count_in,
                        const float* __restrict__ mean_in,
                        const float* __restrict__ cov_in) {
    int c = blockIdx.x;
    int t = threadIdx.x;   // 0..191
    int mraw = g_cnt[c];
    __syncthreads();                   // ALL threads read g_cnt[c] before reset
    if (t == 0) g_cnt[c] = 0;          // reset for the next launch (deterministic)
    float cnt = (float)mraw;
    int m = (mraw < BINW) ? mraw : BINW;
    const int* bin = g_bin + c * BINW;

    float4 s = make_float4(0.f, 0.f, 0.f, 0.f);
    float4 q = make_float4(0.f, 0.f, 0.f, 0.f);

    int i = 0;
    for (; i + 4 <= m; i += 4) {
        int n0 = bin[i], n1 = bin[i + 1], n2 = bin[i + 2], n3 = bin[i + 3];
        float4 v0 = ((const float4*)(feats + (long)n0 * AA))[t];
        float4 v1 = ((const float4*)(feats + (long)n1 * AA))[t];
        float4 v2 = ((const float4*)(feats + (long)n2 * AA))[t];
        float4 v3 = ((const float4*)(feats + (long)n3 * AA))[t];
        s.x += v0.x + v1.x + v2.x + v3.x;
        s.y += v0.y + v1.y + v2.y + v3.y;
        s.z += v0.z + v1.z + v2.z + v3.z;
        s.w += v0.w + v1.w + v2.w + v3.w;
        q.x += v0.x * v0.x + v1.x * v1.x + v2.x * v2.x + v3.x * v3.x;
        q.y += v0.y * v0.y + v1.y * v1.y + v2.y * v2.y + v3.y * v3.y;
        q.z += v0.z * v0.z + v1.z * v1.z + v2.z * v2.z + v3.z * v3.z;
        q.w += v0.w * v0.w + v1.w * v1.w + v2.w * v2.w + v3.w * v3.w;
    }
    for (; i < m; i++) {
        float4 v = ((const float4*)(feats + (long)bin[i] * AA))[t];
        s.x += v.x; s.y += v.y; s.z += v.z; s.w += v.w;
        q.x += v.x * v.x; q.y += v.y * v.y;
        q.z += v.z * v.z; q.w += v.w * v.w;
    }

    float amount = fmaxf(cnt, 1.0f);
    float denom = cnt + count_in[c];
    float w = (denom > 0.0f) ? (cnt / fmaxf(denom, 1.0f)) : 0.0f;
    float omw = 1.0f - w;

    float sums[4] = {s.x, s.y, s.z, s.w};
    float sqs[4]  = {q.x, q.y, q.z, q.w};
    float nc[4], pv[4], wsq[4], wm2[4];
    float t3 = 0.0f;
#pragma unroll
    for (int j = 0; j < 4; j++) {
        int a = 4 * t + j;
        long idx = (long)c * AA + a;
        float ave = sums[j] / amount;
        float var = (sqs[j] - 2.0f * ave * sums[j] + cnt * ave * ave) / amount;
        float d = mean_in[idx] - ave;
        float v = cov_in[idx] * omw + var * w + w * omw * d * d;
        float wv = W[idx];
        nc[j] = v;
        pv[j] = wv * v;
        wsq[j] = wv * wv;
        wm2[j] = -2.0f * wv;
        t3 += wv * wv * v;
    }
    long o2 = (long)c * AA2 + 2 * t;
    g_Acov[o2]     = packbf2(nc[0], nc[1]);
    g_Acov[o2 + 1] = packbf2(nc[2], nc[3]);
    g_AP[o2]       = packbf2(pv[0], pv[1]);
    g_AP[o2 + 1]   = packbf2(pv[2], pv[3]);
    g_Bsq[o2]      = packbf2(wsq[0], wsq[1]);
    g_Bsq[o2 + 1]  = packbf2(wsq[2], wsq[3]);
    g_Bm2[o2]      = packbf2(wm2[0], wm2[1]);
    g_Bm2[o2 + 1]  = packbf2(wm2[2], wm2[3]);

    __shared__ float stot;
    if (t == 0) stot = 0.f;
    __syncthreads();
#pragma unroll
    for (int d2 = 16; d2 > 0; d2 >>= 1)
        t3 += __shfl_down_sync(0xffffffffu, t3, d2);
    if ((t & 31) == 0) atomicAdd(&stot, t3);
    __syncthreads();
    if (t == 0) g_T3[c] = stot;
}

// ---------------- tensor-core GEMM (bf16 m16n8k16, ldmatrix, phase-split-K) ----------------
// z=0: S1 = hr*(cov @ (W^2)^T + T3)   z=1: S2 = hr*(P @ (-2W)^T)
// Block 128(m) x 64(n), 256 threads = 8 warps (4m x 2n), warp tile 32x32.
// 3-buffer cp.async ring, ONE __syncthreads per stage, wait_group 1.
#define BM 128
#define BN 64
#define BKU 16   // u32 words per row per stage (= 32 bf16)
#define LDK 20   // padded u32 stride; ldmatrix-conflict-free
#define NSTG 3
#define STAGES (AA2 / BKU)   // 24
__global__ void __launch_bounds__(256, 2)
k_gemm_t(const float* __restrict__ ratio) {
    __shared__ unsigned sA[NSTG][BM * LDK];
    __shared__ unsigned sB[NSTG][BN * LDK];

    int tid = threadIdx.x;
    int bm = blockIdx.y * BM;
    int bn = blockIdx.x * BN;
    int z  = blockIdx.z;
    int lane = tid & 31;
    int warp = tid >> 5;
    int wm = (warp >> 1) * 32;
    int wn = (warp & 1) * 32;
    int grp = lane >> 2;
    int tig = lane & 3;

    const unsigned* Asrc = z ? g_AP : g_Acov;
    const unsigned* Bsrc = z ? g_Bm2 : g_Bsq;
    float* Sdst = z ? g_S2 : g_S1;

    int ar = tid >> 1;
    int ak = (tid & 1) * 8;
    int agm = bm + ar; if (agm >= CC) agm = CC - 1;
    int br = tid >> 2;
    int bk = (tid & 3) * 4;
    int bgn = bn + br; if (bgn >= CC) bgn = CC - 1;

    unsigned sa_dst[NSTG], sb_dst[NSTG];
#pragma unroll
    for (int b = 0; b < NSTG; b++) {
        sa_dst[b] = (unsigned)__cvta_generic_to_shared(&sA[b][ar * LDK + ak]);
        sb_dst[b] = (unsigned)__cvta_generic_to_shared(&sB[b][br * LDK + bk]);
    }

    int a_row_off = (lane & 7) + ((lane >> 3 & 1) << 3);
    int a_word    = (lane >> 4) << 2;
    int b_row_off = ((lane >> 4) << 3) + (lane & 7);
    int b_word    = ((lane >> 3) & 1) << 2;

    unsigned sA_base = (unsigned)__cvta_generic_to_shared(&sA[0][0]);
    unsigned sB_base = (unsigned)__cvta_generic_to_shared(&sB[0][0]);

    float acc[2][4][4];
#pragma unroll
    for (int mi = 0; mi < 2; mi++)
#pragma unroll
        for (int ni = 0; ni < 4; ni++)
#pragma unroll
            for (int q = 0; q < 4; q++) acc[mi][ni][q] = 0.f;

    auto issue = [&](int s, int buf) {
        int k0 = s * BKU;
        const unsigned* ap = Asrc + (long)agm * AA2 + k0 + ak;
        cpa16(sa_dst[buf], ap);
        cpa16(sa_dst[buf] + 16, ap + 4);
        cpa16(sb_dst[buf], Bsrc + (long)bgn * AA2 + k0 + bk);
        asm volatile("cp.async.commit_group;");
    };

    issue(0, 0);
    issue(1, 1);

    int buf = 0;
    int nbuf = 2;
    for (int s = 0; s < STAGES; s++) {
        if (s + 1 < STAGES) {
            asm volatile("cp.async.wait_group 1;");
        } else {
            asm volatile("cp.async.wait_group 0;");
        }
        __syncthreads();
        if (s + 2 < STAGES) issue(s + 2, nbuf);

        unsigned abase = sA_base + (buf * BM * LDK) * 4u;
        unsigned bbase = sB_base + (buf * BN * LDK) * 4u;
#pragma unroll
        for (int kk = 0; kk < 2; kk++) {
            int k8 = kk * 8;
            unsigned af[2][4];
#pragma unroll
            for (int mi = 0; mi < 2; mi++) {
                int rb = wm + mi * 16;
                unsigned addr = abase +
                    ((rb + a_row_off) * LDK + k8 + a_word) * 4u;
                ldsm4(af[mi][0], af[mi][1], af[mi][2], af[mi][3], addr);
            }
            unsigned bf[4][2];
#pragma unroll
            for (int np = 0; np < 2; np++) {
                int nb = wn + np * 16;
                unsigned addr = bbase +
                    ((nb + b_row_off) * LDK + k8 + b_word) * 4u;
                ldsm4(bf[np * 2][0], bf[np * 2][1],
                      bf[np * 2 + 1][0], bf[np * 2 + 1][1], addr);
            }
#pragma unroll
            for (int mi = 0; mi < 2; mi++)
#pragma unroll
                for (int ni = 0; ni < 4; ni++) {
                    float* c = acc[mi][ni];
                    asm volatile(
                        "mma.sync.aligned.m16n8k16.row.col.f32.bf16.bf16.f32 "
                        "{%0,%1,%2,%3}, {%4,%5,%6,%7}, {%8,%9}, {%0,%1,%2,%3};"
                        : "+f"(c[0]), "+f"(c[1]), "+f"(c[2]), "+f"(c[3])
                        : "r"(af[mi][0]), "r"(af[mi][1]),
                          "r"(af[mi][2]), "r"(af[mi][3]),
                          "r"(bf[ni][0]), "r"(bf[ni][1]));
                }
        }
        buf = (buf == NSTG - 1) ? 0 : buf + 1;
        nbuf = (nbuf == NSTG - 1) ? 0 : nbuf + 1;
    }

    float hr = 0.5f * ratio[0];
#pragma unroll
    for (int mi = 0; mi < 2; mi++) {
        int gm0 = bm + wm + mi * 16 + grp;
        int gm1 = gm0 + 8;
        float t30 = 0.f, t31 = 0.f;
        if (z == 0) {                  // fold T3 into S1
            t30 = (gm0 < CC) ? g_T3[gm0] : 0.f;
            t31 = (gm1 < CC) ? g_T3[gm1] : 0.f;
        }
#pragma unroll
        for (int ni = 0; ni < 4; ni++) {
            int gn = bn + wn + ni * 8 + tig * 2;
            if (gn < CC) {
                if (gm0 < CC)
                    *(float2*)&Sdst[(long)gm0 * CC + gn] =
                        make_float2(hr * (acc[mi][ni][0] + t30),
                                    hr * (acc[mi][ni][1] + t30));
                if (gm1 < CC)
                    *(float2*)&Sdst[(long)gm1 * CC + gn] =
                        make_float2(hr * (acc[mi][ni][2] + t31),
                                    hr * (acc[mi][ni][3] + t31));
            }
        }
    }
}

// ---------------- epilogue: out[n,c] = y[n,c] + S1[lab,c] + S2[lab,c] ----------------
// Streaming cache hints: y/out are touched exactly once (evict-first), S1/S2
// stay default so the 1000 hot rows remain L2-resident for the 16x reuse.
#define C4 (CC / 4)            // 250 float4 per row
#define TOT4 (NN * C4)         // 4,096,000
#define QUART (TOT4 / 4)       // 1,024,000
__global__ void k_out(const float* __restrict__ y,
                      const int* __restrict__ labels,
                      float* __restrict__ out) {
    int idx = blockIdx.x * blockDim.x + threadIdx.x;
    if (idx >= QUART) return;
    int j[4], n[4], c4[4], l[4];
#pragma unroll
    for (int u = 0; u < 4; u++) {
        j[u] = idx + u * QUART;
        n[u] = j[u] / C4;
        c4[u] = j[u] - n[u] * C4;
        l[u] = clamp_class(labels[n[u]]);
    }
    float4 a[4], b1[4], b2[4];
#pragma unroll
    for (int u = 0; u < 4; u++) a[u] = __ldcs(&((const float4*)y)[j[u]]);
#pragma unroll
    for (int u = 0; u < 4; u++) {
        b1[u] = ((const float4*)(g_S1 + (long)l[u] * CC))[c4[u]];
        b2[u] = ((const float4*)(g_S2 + (long)l[u] * CC))[c4[u]];
    }
#pragma unroll
    for (int u = 0; u < 4; u++) {
        a[u].x += b1[u].x + b2[u].x;
        a[u].y += b1[u].y + b2[u].y;
        a[u].z += b1[u].z + b2[u].z;
        a[u].w += b1[u].w + b2[u].w;
        __stcs(&((float4*)out)[j[u]], a[u]);
    }
}

// ---------------- launch ----------------
extern "C" void kernel_launch(void* const* d_in, const int* in_sizes, int n_in,
                              void* d_out, int out_size) {
    const float* y      = (const float*)d_in[0];
    const float* feats  = (const float*)d_in[1];
    const float* W      = (const float*)d_in[2];
    const int*   labels = (const int*)d_in[3];   // JAX x64 disabled -> int32
    const float* count  = (const float*)d_in[4];
    const float* mean   = (const float*)d_in[5];
    const float* cov    = (const float*)d_in[6];
    const float* ratio  = (const float*)d_in[7];
    float* out = (float*)d_out;

    k_scatter<<<NN / 256, 256>>>(labels);
    k_stats<<<CC, 192>>>(feats, W, count, mean, cov);
    k_gemm_t<<<dim3((CC + BN - 1) / BN, (CC + BM - 1) / BM, 2), 256>>>(ratio);
    k_out<<<(QUART + 255) / 256, 256>>>(y, labels, out);
}